// round 13
// baseline (speedup 1.0000x reference)
#include <cuda_runtime.h>
#include <cuda_bf16.h>
#include <cstdint>

#define BINS 10

static __device__ float        g_cnt[BINS];
static __device__ float        g_sum[BINS];
static __device__ unsigned int g_ticket;

#define WARPS_PER_BLOCK 4
#define SLOT_F4 256        // 250 used for C=1000, padded

__device__ __forceinline__ void cp16(unsigned smem_dst, const void* gmem_src) {
    asm volatile("cp.async.cg.shared.global [%0], [%1], 16;\n"
                 :: "r"(smem_dst), "l"(gmem_src));
}
__device__ __forceinline__ void cp_commit() {
    asm volatile("cp.async.commit_group;\n" ::: "memory");
}
__device__ __forceinline__ void cp_wait1() {
    asm volatile("cp.async.wait_group 1;\n" ::: "memory");
}
__device__ __forceinline__ void cp_wait0() {
    asm volatile("cp.async.wait_group 0;\n" ::: "memory");
}

// Warp-per-row, grid-strided, cp.async double-buffered smem staging.
// Loads have no register destination -> next row streams while this row's
// exps run; per-warp WAR serialization (the R8-R11 limiter) is gone.
__global__ __launch_bounds__(WARPS_PER_BLOCK * 32) void ghm_fused(
    const float* __restrict__ pred,
    const int*   __restrict__ target,   // JAX int64 -> int32 (x64 disabled)
    float*       __restrict__ out,
    int B, int C)
{
    __shared__ float4 buf[WARPS_PER_BLOCK * 2 * SLOT_F4];  // 32 KB
    __shared__ float  s_cnt[BINS];
    __shared__ float  s_sum[BINS];
    __shared__ bool   s_last;
    if (threadIdx.x < BINS) { s_cnt[threadIdx.x] = 0.0f; s_sum[threadIdx.x] = 0.0f; }
    if (threadIdx.x == 0) s_last = false;
    __syncthreads();

    const int warp = threadIdx.x >> 5;
    const int lane = threadIdx.x & 31;
    const int n4   = C >> 2;                         // 250 for C=1000
    const int gw   = blockIdx.x * WARPS_PER_BLOCK + warp;
    const int nw   = gridDim.x * WARPS_PER_BLOCK;

    // smem byte address of this warp's two slots
    const unsigned slot_base =
        (unsigned)__cvta_generic_to_shared(&buf[warp * 2 * SLOT_F4]);

    // Prologue: stage first row into slot 0.
    if (gw < B) {
        const float4* src = (const float4*)(pred + (size_t)gw * (size_t)C);
        for (int j = lane; j < n4; j += 32)
            cp16(slot_base + (unsigned)j * 16u, src + j);
        cp_commit();
    }

    int k = 0;
    for (int r = gw; r < B; r += nw, ++k) {
        const int rn = r + nw;
        if (rn < B) {  // stage next row into the other slot
            const unsigned dst = slot_base + (unsigned)(((k + 1) & 1) * SLOT_F4) * 16u;
            const float4* src = (const float4*)(pred + (size_t)rn * (size_t)C);
            for (int j = lane; j < n4; j += 32)
                cp16(dst + (unsigned)j * 16u, src + j);
            cp_commit();
            cp_wait1();          // current row's group done, next stays in flight
        } else {
            cp_wait0();
        }
        __syncwarp();            // all lanes' copies visible warp-wide

        const float4* slot = &buf[(warp * 2 + (k & 1)) * SLOT_F4];
        float s = 0.0f;
        #pragma unroll 4
        for (int j = lane; j < n4; j += 32) {
            const float4 v = slot[j];
            s += __expf(v.x) + __expf(v.y) + __expf(v.z) + __expf(v.w);
        }
        // tail for C % 4 != 0 (not hit for C=1000): direct global loads
        for (int j = (n4 << 2) + lane; j < C; j += 32)
            s += __expf(pred[(size_t)r * (size_t)C + j]);

        #pragma unroll
        for (int o = 16; o; o >>= 1) s += __shfl_xor_sync(0xffffffffu, s, o);

        if (lane == 0) {
            int t = target[r];
            t = t < 0 ? 0 : (t >= C ? C - 1 : t);        // crash-guard
            const float tv = ((const float*)slot)[t];    // from smem, no gmem gather
            const float g = 1.0f - __expf(tv) / s;
            int b = (int)floorf(g * 10.0f);
            b = b < 0 ? 0 : (b > BINS - 1 ? BINS - 1 : b);
            const float loss = -tv + __logf(s + 1e-8f);
            atomicAdd(&s_cnt[b], 1.0f);
            atomicAdd(&s_sum[b], loss);
        }
        __syncwarp();
    }

    __syncthreads();
    if (threadIdx.x < BINS) {
        const float c = s_cnt[threadIdx.x];
        if (c != 0.0f) {
            atomicAdd(&g_cnt[threadIdx.x], c);
            atomicAdd(&g_sum[threadIdx.x], s_sum[threadIdx.x]);
        }
    }

    // Last-block ticket: finalize + reset for the next graph replay.
    __threadfence();
    __syncthreads();
    if (threadIdx.x == 0) {
        const unsigned int tk = atomicAdd(&g_ticket, 1u);
        s_last = (tk == gridDim.x - 1u);
    }
    __syncthreads();

    if (s_last && threadIdx.x == 0) {
        float n_nonempty = 0.0f;
        float tot = 0.0f;
        #pragma unroll
        for (int b = 0; b < BINS; ++b) {
            const float c = __ldcg(&g_cnt[b]);
            const float l = __ldcg(&g_sum[b]);
            if (c > 0.0f) { n_nonempty += 1.0f; tot += l / c; }
        }
        out[0] = tot / fmaxf(n_nonempty, 1.0f);
        #pragma unroll
        for (int b = 0; b < BINS; ++b) { __stcg(&g_cnt[b], 0.0f); __stcg(&g_sum[b], 0.0f); }
        __threadfence();
        __stcg(&g_ticket, 0u);
    }
}

extern "C" void kernel_launch(void* const* d_in, const int* in_sizes, int n_in,
                              void* d_out, int out_size) {
    const float* pred   = (const float*)d_in[0];
    const int*   target = (const int*)d_in[1];
    float*       out    = (float*)d_out;

    const int B = in_sizes[1];            // 65536 rows
    const int C = in_sizes[0] / B;        // 1000 classes

    // Persistent-ish grid: ~7 blocks/SM (32KB smem each) on 148 SMs.
    int grid = 148 * 7;
    const int max_grid = (B + WARPS_PER_BLOCK - 1) / WARPS_PER_BLOCK;
    if (grid > max_grid) grid = max_grid;

    ghm_fused<<<grid, WARPS_PER_BLOCK * 32>>>(pred, target, out, B, C);
}